// round 3
// baseline (speedup 1.0000x reference)
#include <cuda_runtime.h>
#include <cuda_bf16.h>
#include <math.h>

// ---------------- problem constants ----------------
#define BB   256
#define LL   512
#define CC   32
#define NB   4
#define SEG  64
#define FREQ 8
#define STEP 4
#define DD   512
#define HH   1024
#define FIN  2048   // SEG*CC
#define FF   257    // L/2+1

// ---------------- scratch layout (floats) ----------------
static constexpr long OFF_MEAN  = 0;
static constexpr long OFF_STD   = OFF_MEAN  + 8192;
static constexpr long OFF_XNC   = OFF_STD   + 8192;
static constexpr long OFF_KKER  = OFF_XNC   + 8192L*512;
static constexpr long OFF_KC    = OFF_KKER  + 4L*512;
static constexpr long OFF_D1    = OFF_KC    + 4L*512*512;      // 4M floats
static constexpr long OFF_XI    = OFF_D1    + 4L*1024*1024;
static constexpr long OFF_E1    = OFF_XI    + 4L*2048*2048;
static constexpr long OFF_ENC   = OFF_E1    + 4L*2048*1024;
static constexpr long OFF_Y     = OFF_ENC   + 4L*2048*512;
static constexpr long OFF_HA    = OFF_Y     + 4L*2048*512;
static constexpr long OFF_HB    = OFF_HA    + 4L*256*512;
static constexpr long OFF_PREDS = OFF_HB    + 4L*256*512;
static constexpr long OFF_DEC   = OFF_PREDS + 4L*256*4*512;
static constexpr long SCRATCH_TOTAL = OFF_DEC + 4L*1024*2048;

__device__ __align__(16) float g_scratch[SCRATCH_TOTAL];

// ---------------- f32x2 helpers ----------------
union F2U { unsigned long long u; float2 f; };
__device__ __forceinline__ unsigned long long pack2(float x, float y) {
    F2U t; t.f.x = x; t.f.y = y; return t.u;
}
__device__ __forceinline__ float2 unpack2(unsigned long long u) {
    F2U t; t.u = u; return t.f;
}
__device__ __forceinline__ void ffma2(unsigned long long& d, unsigned long long a,
                                      unsigned long long b) {
    asm("fma.rn.f32x2 %0, %1, %2, %0;" : "+l"(d) : "l"(a), "l"(b));
}

// ---------------- instance-norm stats + transposed normalized input ----------------
// xnc[(b*32+c)][l] = (x[b][l][c]-mean[b][c]) / std[b][c]
__global__ void stats_xnc_kernel(const float* __restrict__ x, float* __restrict__ xnc,
                                 float* __restrict__ meanO, float* __restrict__ stdO)
{
    int b   = blockIdx.x;
    int tid = threadIdx.x;         // 256
    int c   = tid & 31;
    int ty  = tid >> 5;            // 0..7
    const float* xb = x + (long)b * LL * CC;

    float s = 0.f, s2 = 0.f;
    for (int l = ty; l < LL; l += 8) {
        float v = xb[l * CC + c];
        s += v; s2 += v * v;
    }
    __shared__ float sm[8][32], sm2[8][32];
    sm[ty][c] = s; sm2[ty][c] = s2;
    __syncthreads();
    __shared__ float smean[32], sinv[32];
    if (ty == 0) {
        float S = 0.f, S2 = 0.f;
        #pragma unroll
        for (int i = 0; i < 8; i++) { S += sm[i][c]; S2 += sm2[i][c]; }
        float mu  = S * (1.f / LL);
        float var = S2 * (1.f / LL) - mu * mu;
        float sd  = sqrtf(var + 1e-5f);
        smean[c] = mu; sinv[c] = 1.f / sd;
        meanO[b * 32 + c] = mu;
        stdO [b * 32 + c] = sd;
    }
    __syncthreads();

    __shared__ float tile[32][33];
    for (int l0 = 0; l0 < LL; l0 += 32) {
        #pragma unroll
        for (int i = 0; i < 4; i++) {
            int l = l0 + ty + i * 8;
            tile[ty + i * 8][c] = (xb[l * CC + c] - smean[c]) * sinv[c];
        }
        __syncthreads();
        #pragma unroll
        for (int i = 0; i < 4; i++) {
            int cc = ty + i * 8;
            int ll = c;
            xnc[((long)b * 32 + cc) * LL + l0 + ll] = tile[ll][cc];
        }
        __syncthreads();
    }
}

// ---------------- circular-convolution kernel from mask ----------------
__global__ void kker_kernel(const float* __restrict__ mw, float* __restrict__ kker)
{
    int nb = blockIdx.x;
    int d  = threadIdx.x;          // 512
    __shared__ float m[FF];
    for (int f = threadIdx.x; f < FF; f += 512)
        m[f] = 1.f / (1.f + expf(-mw[nb * FF + f]));
    __syncthreads();
    float acc = m[0] + m[256] * ((d & 1) ? -1.f : 1.f);
    for (int f = 1; f < 256; f++) {
        int k = (f * d) & 511;
        acc += 2.f * m[f] * cospif((float)k * (1.f / 256.f));
    }
    kker[nb * 512 + d] = acc * (1.f / 512.f);
}

// Kc[nb][l][lp] = kker[nb][(l-lp) mod 512]
__global__ void kc_kernel(const float* __restrict__ kker, float* __restrict__ Kc)
{
    int nb = blockIdx.y, l = blockIdx.x;
    __shared__ float kr[512];
    kr[threadIdx.x] = kker[nb * 512 + threadIdx.x];
    __syncthreads();
    int lp = threadIdx.x;
    Kc[((long)nb * 512 + l) * 512 + lp] = kr[(l - lp + 512) & 511];
}

// ---------------- FFMA2 tiled NT GEMM:  C = A(MxK) @ B(NxK)^T (+bias)(+D)(relu) ----------------
// XIPERM: instead of C[m*ldc+n], store to the encoder-input permutation:
//   idx = ((n>>5)*8 + (m>>6))*2048 + (m&63)*32 + (n&31)   (per z block of 2048*2048)
template<int BM, int BN, int BK, int TM, int TN, bool RELU, bool XIPERM>
__global__ void __launch_bounds__((BM/TM)*(BN/TN))
gemm2_nt(const float* __restrict__ A, const float* __restrict__ Bw,
         const float* __restrict__ bias, const float* __restrict__ Dadd,
         float* __restrict__ C,
         int K, int lda, int ldb, int ldc, int ldd,
         long sA, long sB, long sBias, long sD, long sC)
{
    constexpr int TX = BN / TN, TY = BM / TM, THREADS = TX * TY;
    static_assert(TN % 4 == 0 && TM % 4 == 0, "tile shape");
    __shared__ __align__(16) float As[BK][BM + 4];
    __shared__ __align__(16) float Bs[BK][BN + 4];

    long z = blockIdx.z;
    A  += z * sA;
    Bw += z * sB;
    C  += z * sC;
    if (bias) bias += z * sBias;
    if (Dadd) Dadd += z * sD;

    const int bm = blockIdx.y * BM, bn = blockIdx.x * BN;
    const int tid = threadIdx.x;
    const int tx = tid % TX, ty = tid / TX;

    unsigned long long acc[TM][TN / 2];
    #pragma unroll
    for (int i = 0; i < TM; i++)
        #pragma unroll
        for (int q = 0; q < TN / 2; q++) acc[i][q] = 0ull;

    const float* Aptr = A  + (long)bm * lda;
    const float* Bptr = Bw + (long)bn * ldb;

    for (int k0 = 0; k0 < K; k0 += BK) {
        #pragma unroll
        for (int li = tid; li < BM * (BK / 4); li += THREADS) {
            int row = li / (BK / 4), kq = li % (BK / 4);
            float4 v = *(const float4*)(Aptr + (long)row * lda + k0 + kq * 4);
            As[kq*4+0][row] = v.x; As[kq*4+1][row] = v.y;
            As[kq*4+2][row] = v.z; As[kq*4+3][row] = v.w;
        }
        #pragma unroll
        for (int li = tid; li < BN * (BK / 4); li += THREADS) {
            int row = li / (BK / 4), kq = li % (BK / 4);
            float4 v = *(const float4*)(Bptr + (long)row * ldb + k0 + kq * 4);
            Bs[kq*4+0][row] = v.x; Bs[kq*4+1][row] = v.y;
            Bs[kq*4+2][row] = v.z; Bs[kq*4+3][row] = v.w;
        }
        __syncthreads();
        #pragma unroll
        for (int kk = 0; kk < BK; kk++) {
            unsigned long long ad[TM];
            #pragma unroll
            for (int i = 0; i < TM; i += 4) {
                float4 t4 = *(const float4*)&As[kk][ty * TM + i];
                ad[i]   = pack2(t4.x, t4.x);
                ad[i+1] = pack2(t4.y, t4.y);
                ad[i+2] = pack2(t4.z, t4.z);
                ad[i+3] = pack2(t4.w, t4.w);
            }
            unsigned long long bd[TN / 2];
            #pragma unroll
            for (int j = 0; j < TN; j += 4) {
                ulonglong2 t2 = *(const ulonglong2*)&Bs[kk][tx * TN + j];
                bd[j/2]     = t2.x;
                bd[j/2 + 1] = t2.y;
            }
            #pragma unroll
            for (int i = 0; i < TM; i++)
                #pragma unroll
                for (int q = 0; q < TN / 2; q++)
                    ffma2(acc[i][q], ad[i], bd[q]);
        }
        __syncthreads();
    }

    #pragma unroll
    for (int i = 0; i < TM; i++) {
        int m = bm + ty * TM + i;
        float vout[TN];
        #pragma unroll
        for (int q = 0; q < TN / 2; q++) {
            float2 v = unpack2(acc[i][q]);
            vout[2*q] = v.x; vout[2*q+1] = v.y;
        }
        #pragma unroll
        for (int j = 0; j < TN; j += 4) {
            int n = bn + tx * TN + j;
            float4 o;
            o.x = vout[j]; o.y = vout[j+1]; o.z = vout[j+2]; o.w = vout[j+3];
            if (bias) {
                float4 b4 = *(const float4*)&bias[n];
                o.x += b4.x; o.y += b4.y; o.z += b4.z; o.w += b4.w;
            }
            if (Dadd) {
                float4 d4 = *(const float4*)&Dadd[(long)m * ldd + n];
                o.x += d4.x; o.y += d4.y; o.z += d4.z; o.w += d4.w;
            }
            if (RELU) {
                o.x = fmaxf(o.x, 0.f); o.y = fmaxf(o.y, 0.f);
                o.z = fmaxf(o.z, 0.f); o.w = fmaxf(o.w, 0.f);
            }
            if (XIPERM) {
                long idx = ((long)((n >> 5) * 8 + (m >> 6))) * 2048 + (m & 63) * 32 + (n & 31);
                *(float4*)&C[idx] = o;
            } else {
                *(float4*)&C[(long)m * ldc + n] = o;
            }
        }
    }
}

// ---------------- LayerNorm over last dim 512 ----------------
__global__ void ln_kernel(float* __restrict__ preds, const float* __restrict__ g,
                          const float* __restrict__ bb)
{
    long row = blockIdx.x;                  // nb*1024 + b*4 + s
    int nb = (int)(row >> 10);
    float* p = preds + row * 512;
    int t = threadIdx.x;                    // 256
    float v0 = p[t], v1 = p[t + 256];
    float s = v0 + v1, s2 = v0 * v0 + v1 * v1;
    #pragma unroll
    for (int o = 16; o; o >>= 1) {
        s  += __shfl_xor_sync(0xFFFFFFFFu, s,  o);
        s2 += __shfl_xor_sync(0xFFFFFFFFu, s2, o);
    }
    __shared__ float ws[8], ws2[8];
    if ((t & 31) == 0) { ws[t >> 5] = s; ws2[t >> 5] = s2; }
    __syncthreads();
    float S = 0.f, S2 = 0.f;
    #pragma unroll
    for (int i = 0; i < 8; i++) { S += ws[i]; S2 += ws2[i]; }
    float mu  = S * (1.f / 512.f);
    float inv = rsqrtf(S2 * (1.f / 512.f) - mu * mu + 1e-5f);
    p[t]       = (v0 - mu) * inv * g[nb * 512 + t]       + bb[nb * 512 + t];
    p[t + 256] = (v1 - mu) * inv * g[nb * 512 + t + 256] + bb[nb * 512 + t + 256];
}

// ---------------- sum over blocks + de-normalize ----------------
__global__ void combine_kernel(const float* __restrict__ Dec, const float* __restrict__ stdv,
                               const float* __restrict__ meanv, float* __restrict__ out)
{
    long o = (long)blockIdx.x * 256 + threadIdx.x;   // b*8192 + (s*64+p)*32 + c
    int b = (int)(o >> 13);
    int r = (int)(o & 8191);
    int t = r >> 5, c = r & 31;
    int s = t >> 6, p = t & 63;
    long idx = ((long)(b * 4 + s)) * 2048 + p * 32 + c;
    const long NBS = 1024L * 2048;
    float acc = Dec[idx] + Dec[idx + NBS] + Dec[idx + 2 * NBS] + Dec[idx + 3 * NBS];
    out[o] = acc * stdv[b * 32 + c] + meanv[b * 32 + c];
}

// ---------------- host orchestration ----------------
extern "C" void kernel_launch(void* const* d_in, const int* in_sizes, int n_in,
                              void* d_out, int out_size)
{
    const float* x_enc  = (const float*)d_in[0];
    const float* mask_w = (const float*)d_in[4];
    const float* enc_w1 = (const float*)d_in[5];
    const float* enc_b1 = (const float*)d_in[6];
    const float* enc_w2 = (const float*)d_in[7];
    const float* enc_b2 = (const float*)d_in[8];
    const float* wxh    = (const float*)d_in[9];
    const float* whh    = (const float*)d_in[10];
    const float* ln_g   = (const float*)d_in[11];
    const float* ln_b   = (const float*)d_in[12];
    const float* dec_w1 = (const float*)d_in[13];
    const float* dec_b1 = (const float*)d_in[14];
    const float* dec_w2 = (const float*)d_in[15];
    const float* dec_b2 = (const float*)d_in[16];

    float* sc = nullptr;
    cudaGetSymbolAddress((void**)&sc, g_scratch);
    float* g_mean  = sc + OFF_MEAN;
    float* g_std   = sc + OFF_STD;
    float* g_xnc   = sc + OFF_XNC;
    float* g_kker  = sc + OFF_KKER;
    float* g_kc    = sc + OFF_KC;
    float* g_xi    = sc + OFF_XI;
    float* g_e1    = sc + OFF_E1;
    float* g_enc   = sc + OFF_ENC;
    float* g_y     = sc + OFF_Y;
    float* g_ha    = sc + OFF_HA;
    float* g_hb    = sc + OFF_HB;
    float* g_preds = sc + OFF_PREDS;
    float* g_d1    = sc + OFF_D1;
    float* g_dec   = sc + OFF_DEC;

    // 1) instance norm stats + normalized transposed input
    stats_xnc_kernel<<<256, 256>>>(x_enc, g_xnc, g_mean, g_std);

    // 2) circulant kernel + matrix
    kker_kernel<<<4, 512>>>(mask_w, g_kker);
    kc_kernel<<<dim3(512, 4), 512>>>(g_kker, g_kc);

    // 3) Fourier filter GEMM, epilogue-fused permutation straight into Xi layout
    gemm2_nt<128, 128, 16, 8, 8, false, true><<<dim3(8192 / 128, 512 / 128, NB), 256>>>(
        g_kc, g_xnc, nullptr, nullptr, g_xi,
        512, 512, 512, 0, 0,
        512L * 512, 0, 0, 0, 2048L * 2048);

    // 4) encoder MLP
    gemm2_nt<128, 128, 16, 8, 8, true, false><<<dim3(1024 / 128, 2048 / 128, NB), 256>>>(
        g_xi, enc_w1, enc_b1, nullptr, g_e1,
        2048, 2048, 2048, 1024, 0,
        2048L * 2048, 1024L * 2048, 1024, 0, 2048L * 1024);
    gemm2_nt<128, 128, 16, 8, 8, false, false><<<dim3(512 / 128, 2048 / 128, NB), 256>>>(
        g_e1, enc_w2, enc_b2, nullptr, g_enc,
        1024, 1024, 1024, 512, 0,
        2048L * 1024, 512L * 1024, 512, 0, 2048L * 512);

    // 5) Y = Enc @ Wxh^T  (all timesteps at once)
    gemm2_nt<128, 128, 16, 8, 8, false, false><<<dim3(512 / 128, 2048 / 128, NB), 256>>>(
        g_enc, wxh, nullptr, nullptr, g_y,
        512, 512, 512, 512, 0,
        2048L * 512, 512L * 512, 0, 0, 2048L * 512);

    // 6) RNN recurrence: h_t = h_{t-1} @ Whh^T + Y_t   (h_0 = Y_0)
    float* hbuf[2] = { g_hb, g_ha };   // t odd -> g_ha
    for (int t = 1; t < 8; t++) {
        const float* Aop = (t == 1) ? g_y : hbuf[(t - 1) & 1];
        int  lda_t = (t == 1) ? 4096 : 512;
        long sA_t  = (t == 1) ? 2048L * 512 : 256L * 512;
        gemm2_nt<32, 64, 16, 4, 4, false, false><<<dim3(512 / 64, 256 / 32, NB), 128>>>(
            Aop, whh, nullptr, g_y + t * 512, hbuf[t & 1],
            512, lda_t, 512, 512, 4096,
            sA_t, 512L * 512, 0, 2048L * 512, 256L * 512);
    }

    // 7) free-run predictions: preds_s = preds_{s-1} @ Whh^T  (preds_0 = h_7 in g_ha)
    for (int s = 1; s <= 4; s++) {
        const float* Aop = (s == 1) ? g_ha : (g_preds + (s - 2) * 512);
        int  lda_s = (s == 1) ? 512 : 2048;
        long sA_s  = (s == 1) ? 256L * 512 : 256L * 4 * 512;
        gemm2_nt<32, 64, 16, 4, 4, false, false><<<dim3(512 / 64, 256 / 32, NB), 128>>>(
            Aop, whh, nullptr, nullptr, g_preds + (s - 1) * 512,
            512, lda_s, 512, 2048, 0,
            sA_s, 512L * 512, 0, 0, 256L * 4 * 512);
    }

    // 8) LayerNorm (in place)
    ln_kernel<<<4096, 256>>>(g_preds, ln_g, ln_b);

    // 9) decoder MLP
    gemm2_nt<128, 128, 16, 8, 8, true, false><<<dim3(1024 / 128, 1024 / 128, NB), 256>>>(
        g_preds, dec_w1, dec_b1, nullptr, g_d1,
        512, 512, 512, 1024, 0,
        256L * 4 * 512, 1024L * 512, 1024, 0, 1024L * 1024);
    gemm2_nt<128, 128, 16, 8, 8, false, false><<<dim3(2048 / 128, 1024 / 128, NB), 256>>>(
        g_d1, dec_w2, dec_b2, nullptr, g_dec,
        1024, 1024, 1024, 2048, 0,
        1024L * 1024, 2048L * 1024, 2048, 0, 1024L * 2048);

    // 10) sum blocks, de-normalize, reshape to [B, 256, 32]
    combine_kernel<<<8192, 256>>>(g_dec, g_std, g_mean, (float*)d_out);
}

// round 4
// speedup vs baseline: 1.0084x; 1.0084x over previous
#include <cuda_runtime.h>
#include <cuda_bf16.h>
#include <math.h>

// ---------------- problem constants ----------------
#define BB   256
#define LL   512
#define CC   32
#define NB   4
#define SEG  64
#define FREQ 8
#define STEP 4
#define DD   512
#define HH   1024
#define FIN  2048   // SEG*CC
#define FF   257    // L/2+1

// ---------------- scratch layout (floats) ----------------
static constexpr long OFF_MEAN  = 0;
static constexpr long OFF_STD   = OFF_MEAN  + 8192;
static constexpr long OFF_XNC   = OFF_STD   + 8192;
static constexpr long OFF_KKER  = OFF_XNC   + 8192L*512;
static constexpr long OFF_KC    = OFF_KKER  + 4L*512;
static constexpr long OFF_D1    = OFF_KC    + 4L*512*512;
static constexpr long OFF_XI    = OFF_D1    + 4L*1024*1024;
static constexpr long OFF_E1    = OFF_XI    + 4L*2048*2048;
static constexpr long OFF_ENC   = OFF_E1    + 4L*2048*1024;
static constexpr long OFF_Y     = OFF_ENC   + 4L*2048*512;
static constexpr long OFF_HA    = OFF_Y     + 4L*2048*512;
static constexpr long OFF_HB    = OFF_HA    + 4L*256*512;
static constexpr long OFF_PREDS = OFF_HB    + 4L*256*512;
static constexpr long OFF_DEC   = OFF_PREDS + 4L*256*4*512;
static constexpr long SCRATCH_TOTAL = OFF_DEC + 4L*1024*2048;

__device__ __align__(16) float g_scratch[SCRATCH_TOTAL];

// ---------------- instance-norm stats + transposed normalized input ----------------
__global__ void stats_xnc_kernel(const float* __restrict__ x, float* __restrict__ xnc,
                                 float* __restrict__ meanO, float* __restrict__ stdO)
{
    int b   = blockIdx.x;
    int tid = threadIdx.x;         // 256
    int c   = tid & 31;
    int ty  = tid >> 5;            // 0..7
    const float* xb = x + (long)b * LL * CC;

    float s = 0.f, s2 = 0.f;
    for (int l = ty; l < LL; l += 8) {
        float v = xb[l * CC + c];
        s += v; s2 += v * v;
    }
    __shared__ float sm[8][32], sm2[8][32];
    sm[ty][c] = s; sm2[ty][c] = s2;
    __syncthreads();
    __shared__ float smean[32], sinv[32];
    if (ty == 0) {
        float S = 0.f, S2 = 0.f;
        #pragma unroll
        for (int i = 0; i < 8; i++) { S += sm[i][c]; S2 += sm2[i][c]; }
        float mu  = S * (1.f / LL);
        float var = S2 * (1.f / LL) - mu * mu;
        float sd  = sqrtf(var + 1e-5f);
        smean[c] = mu; sinv[c] = 1.f / sd;
        meanO[b * 32 + c] = mu;
        stdO [b * 32 + c] = sd;
    }
    __syncthreads();

    __shared__ float tile[32][33];
    for (int l0 = 0; l0 < LL; l0 += 32) {
        #pragma unroll
        for (int i = 0; i < 4; i++) {
            int l = l0 + ty + i * 8;
            tile[ty + i * 8][c] = (xb[l * CC + c] - smean[c]) * sinv[c];
        }
        __syncthreads();
        #pragma unroll
        for (int i = 0; i < 4; i++) {
            int cc = ty + i * 8;
            int ll = c;
            xnc[((long)b * 32 + cc) * LL + l0 + ll] = tile[ll][cc];
        }
        __syncthreads();
    }
}

// ---------------- circular-convolution kernel from mask ----------------
__global__ void kker_kernel(const float* __restrict__ mw, float* __restrict__ kker)
{
    int nb = blockIdx.x;
    int d  = threadIdx.x;          // 512
    __shared__ float m[FF];
    for (int f = threadIdx.x; f < FF; f += 512)
        m[f] = 1.f / (1.f + expf(-mw[nb * FF + f]));
    __syncthreads();
    float acc = m[0] + m[256] * ((d & 1) ? -1.f : 1.f);
    for (int f = 1; f < 256; f++) {
        int k = (f * d) & 511;
        acc += 2.f * m[f] * cospif((float)k * (1.f / 256.f));
    }
    kker[nb * 512 + d] = acc * (1.f / 512.f);
}

// Kc[nb][l][lp] = kker[nb][(l-lp) mod 512]
__global__ void kc_kernel(const float* __restrict__ kker, float* __restrict__ Kc)
{
    int nb = blockIdx.y, l = blockIdx.x;
    __shared__ float kr[512];
    kr[threadIdx.x] = kker[nb * 512 + threadIdx.x];
    __syncthreads();
    int lp = threadIdx.x;
    Kc[((long)nb * 512 + l) * 512 + lp] = kr[(l - lp + 512) & 511];
}

// ---------------- 128x128x8 double-buffered scalar SGEMM (NT) ----------------
// C = A(MxK) @ B(NxK)^T (+bias)(+relu); XIPERM: permuted store into Xi layout
//   idx = ((n>>5)*8 + (m>>6))*2048 + (m&63)*32 + (n&31)
template<bool RELU, bool XIPERM>
__global__ void __launch_bounds__(256)
gemm128(const float* __restrict__ A, const float* __restrict__ Bw,
        const float* __restrict__ bias, float* __restrict__ C,
        int K, int lda, int ldb, int ldc,
        long sA, long sB, long sBias, long sC)
{
    __shared__ __align__(16) float As[2][8][128];
    __shared__ __align__(16) float Bs[2][8][128];

    long z = blockIdx.z;
    A  += z * sA;
    Bw += z * sB;
    C  += z * sC;
    if (bias) bias += z * sBias;

    const int bm = blockIdx.y * 128, bn = blockIdx.x * 128;
    const int tid = threadIdx.x;
    const int tx = tid & 15, ty = tid >> 4;

    // global-load mapping: each thread loads one float4 of A and one of B per k-tile
    const int lrow = tid >> 1;           // 0..127
    const int lk   = (tid & 1) * 4;      // 0 or 4
    const float* Ap = A  + (long)(bm + lrow) * lda + lk;
    const float* Bp = Bw + (long)(bn + lrow) * ldb + lk;

    float acc[8][8];
    #pragma unroll
    for (int i = 0; i < 8; i++)
        #pragma unroll
        for (int j = 0; j < 8; j++) acc[i][j] = 0.f;

    // prologue: load first k-tile
    float4 ra = *(const float4*)Ap;
    float4 rb = *(const float4*)Bp;
    As[0][lk+0][lrow] = ra.x; As[0][lk+1][lrow] = ra.y;
    As[0][lk+2][lrow] = ra.z; As[0][lk+3][lrow] = ra.w;
    Bs[0][lk+0][lrow] = rb.x; Bs[0][lk+1][lrow] = rb.y;
    Bs[0][lk+2][lrow] = rb.z; Bs[0][lk+3][lrow] = rb.w;
    __syncthreads();

    int buf = 0;
    for (int k0 = 8; k0 <= K; k0 += 8) {
        const bool has_next = (k0 < K);
        float4 na, nb4;
        if (has_next) {
            na  = *(const float4*)(Ap + k0);
            nb4 = *(const float4*)(Bp + k0);
        }
        #pragma unroll
        for (int kk = 0; kk < 8; kk++) {
            float a[8], b[8];
            *(float4*)&a[0] = *(const float4*)&As[buf][kk][ty * 8];
            *(float4*)&a[4] = *(const float4*)&As[buf][kk][ty * 8 + 4];
            *(float4*)&b[0] = *(const float4*)&Bs[buf][kk][tx * 8];
            *(float4*)&b[4] = *(const float4*)&Bs[buf][kk][tx * 8 + 4];
            #pragma unroll
            for (int i = 0; i < 8; i++)
                #pragma unroll
                for (int j = 0; j < 8; j++)
                    acc[i][j] += a[i] * b[j];
        }
        if (has_next) {
            int nbuf = buf ^ 1;
            As[nbuf][lk+0][lrow] = na.x;  As[nbuf][lk+1][lrow] = na.y;
            As[nbuf][lk+2][lrow] = na.z;  As[nbuf][lk+3][lrow] = na.w;
            Bs[nbuf][lk+0][lrow] = nb4.x; Bs[nbuf][lk+1][lrow] = nb4.y;
            Bs[nbuf][lk+2][lrow] = nb4.z; Bs[nbuf][lk+3][lrow] = nb4.w;
            __syncthreads();
            buf = nbuf;
        }
    }

    // epilogue
    #pragma unroll
    for (int i = 0; i < 8; i++) {
        int m = bm + ty * 8 + i;
        #pragma unroll
        for (int j = 0; j < 8; j += 4) {
            int n = bn + tx * 8 + j;
            float4 o;
            o.x = acc[i][j]; o.y = acc[i][j+1]; o.z = acc[i][j+2]; o.w = acc[i][j+3];
            if (bias) {
                float4 b4 = *(const float4*)&bias[n];
                o.x += b4.x; o.y += b4.y; o.z += b4.z; o.w += b4.w;
            }
            if (RELU) {
                o.x = fmaxf(o.x, 0.f); o.y = fmaxf(o.y, 0.f);
                o.z = fmaxf(o.z, 0.f); o.w = fmaxf(o.w, 0.f);
            }
            if (XIPERM) {
                long idx = ((long)((n >> 5) * 8 + (m >> 6))) * 2048 + (m & 63) * 32 + (n & 31);
                *(float4*)&C[idx] = o;
            } else {
                *(float4*)&C[(long)m * ldc + n] = o;
            }
        }
    }
}

// ---------------- small scalar NT GEMM for RNN steps (known-good R2 path) ----------------
template<int BM, int BN, int BK, int TM, int TN>
__global__ void __launch_bounds__((BM/TM)*(BN/TN))
gemm_small(const float* __restrict__ A, const float* __restrict__ Bw,
           const float* __restrict__ Dadd, float* __restrict__ C,
           int K, int lda, int ldb, int ldc, int ldd,
           long sA, long sB, long sD, long sC)
{
    constexpr int TX = BN / TN, TY = BM / TM, THREADS = TX * TY;
    __shared__ __align__(16) float As[BK][BM + 4];
    __shared__ __align__(16) float Bs[BK][BN + 4];

    long z = blockIdx.z;
    A  += z * sA;
    Bw += z * sB;
    C  += z * sC;
    if (Dadd) Dadd += z * sD;

    const int bm = blockIdx.y * BM, bn = blockIdx.x * BN;
    const int tid = threadIdx.x;
    const int tx = tid % TX, ty = tid / TX;

    float acc[TM][TN];
    #pragma unroll
    for (int i = 0; i < TM; i++)
        #pragma unroll
        for (int j = 0; j < TN; j++) acc[i][j] = 0.f;

    const float* Aptr = A  + (long)bm * lda;
    const float* Bptr = Bw + (long)bn * ldb;

    for (int k0 = 0; k0 < K; k0 += BK) {
        #pragma unroll
        for (int li = tid; li < BM * (BK / 4); li += THREADS) {
            int row = li / (BK / 4), kq = li % (BK / 4);
            float4 v = *(const float4*)(Aptr + (long)row * lda + k0 + kq * 4);
            As[kq*4+0][row] = v.x; As[kq*4+1][row] = v.y;
            As[kq*4+2][row] = v.z; As[kq*4+3][row] = v.w;
        }
        #pragma unroll
        for (int li = tid; li < BN * (BK / 4); li += THREADS) {
            int row = li / (BK / 4), kq = li % (BK / 4);
            float4 v = *(const float4*)(Bptr + (long)row * ldb + k0 + kq * 4);
            Bs[kq*4+0][row] = v.x; Bs[kq*4+1][row] = v.y;
            Bs[kq*4+2][row] = v.z; Bs[kq*4+3][row] = v.w;
        }
        __syncthreads();
        #pragma unroll
        for (int kk = 0; kk < BK; kk++) {
            float a[TM], bv[TN];
            #pragma unroll
            for (int i = 0; i < TM; i += 4) {
                float4 t4 = *(const float4*)&As[kk][ty * TM + i];
                a[i] = t4.x; a[i+1] = t4.y; a[i+2] = t4.z; a[i+3] = t4.w;
            }
            #pragma unroll
            for (int j = 0; j < TN; j += 4) {
                float4 t4 = *(const float4*)&Bs[kk][tx * TN + j];
                bv[j] = t4.x; bv[j+1] = t4.y; bv[j+2] = t4.z; bv[j+3] = t4.w;
            }
            #pragma unroll
            for (int i = 0; i < TM; i++)
                #pragma unroll
                for (int j = 0; j < TN; j++)
                    acc[i][j] += a[i] * bv[j];
        }
        __syncthreads();
    }

    #pragma unroll
    for (int i = 0; i < TM; i++) {
        int m = bm + ty * TM + i;
        #pragma unroll
        for (int j = 0; j < TN; j++) {
            int n = bn + tx * TN + j;
            float v = acc[i][j];
            if (Dadd) v += Dadd[(long)m * ldd + n];
            C[(long)m * ldc + n] = v;
        }
    }
}

// ---------------- LayerNorm over last dim 512 ----------------
__global__ void ln_kernel(float* __restrict__ preds, const float* __restrict__ g,
                          const float* __restrict__ bb)
{
    long row = blockIdx.x;
    int nb = (int)(row >> 10);
    float* p = preds + row * 512;
    int t = threadIdx.x;                    // 256
    float v0 = p[t], v1 = p[t + 256];
    float s = v0 + v1, s2 = v0 * v0 + v1 * v1;
    #pragma unroll
    for (int o = 16; o; o >>= 1) {
        s  += __shfl_xor_sync(0xFFFFFFFFu, s,  o);
        s2 += __shfl_xor_sync(0xFFFFFFFFu, s2, o);
    }
    __shared__ float ws[8], ws2[8];
    if ((t & 31) == 0) { ws[t >> 5] = s; ws2[t >> 5] = s2; }
    __syncthreads();
    float S = 0.f, S2 = 0.f;
    #pragma unroll
    for (int i = 0; i < 8; i++) { S += ws[i]; S2 += ws2[i]; }
    float mu  = S * (1.f / 512.f);
    float inv = rsqrtf(S2 * (1.f / 512.f) - mu * mu + 1e-5f);
    p[t]       = (v0 - mu) * inv * g[nb * 512 + t]       + bb[nb * 512 + t];
    p[t + 256] = (v1 - mu) * inv * g[nb * 512 + t + 256] + bb[nb * 512 + t + 256];
}

// ---------------- sum over blocks + de-normalize ----------------
__global__ void combine_kernel(const float* __restrict__ Dec, const float* __restrict__ stdv,
                               const float* __restrict__ meanv, float* __restrict__ out)
{
    long o = (long)blockIdx.x * 256 + threadIdx.x;
    int b = (int)(o >> 13);
    int r = (int)(o & 8191);
    int t = r >> 5, c = r & 31;
    int s = t >> 6, p = t & 63;
    long idx = ((long)(b * 4 + s)) * 2048 + p * 32 + c;
    const long NBS = 1024L * 2048;
    float acc = Dec[idx] + Dec[idx + NBS] + Dec[idx + 2 * NBS] + Dec[idx + 3 * NBS];
    out[o] = acc * stdv[b * 32 + c] + meanv[b * 32 + c];
}

// ---------------- host orchestration ----------------
extern "C" void kernel_launch(void* const* d_in, const int* in_sizes, int n_in,
                              void* d_out, int out_size)
{
    const float* x_enc  = (const float*)d_in[0];
    const float* mask_w = (const float*)d_in[4];
    const float* enc_w1 = (const float*)d_in[5];
    const float* enc_b1 = (const float*)d_in[6];
    const float* enc_w2 = (const float*)d_in[7];
    const float* enc_b2 = (const float*)d_in[8];
    const float* wxh    = (const float*)d_in[9];
    const float* whh    = (const float*)d_in[10];
    const float* ln_g   = (const float*)d_in[11];
    const float* ln_b   = (const float*)d_in[12];
    const float* dec_w1 = (const float*)d_in[13];
    const float* dec_b1 = (const float*)d_in[14];
    const float* dec_w2 = (const float*)d_in[15];
    const float* dec_b2 = (const float*)d_in[16];

    float* sc = nullptr;
    cudaGetSymbolAddress((void**)&sc, g_scratch);
    float* g_mean  = sc + OFF_MEAN;
    float* g_std   = sc + OFF_STD;
    float* g_xnc   = sc + OFF_XNC;
    float* g_kker  = sc + OFF_KKER;
    float* g_kc    = sc + OFF_KC;
    float* g_xi    = sc + OFF_XI;
    float* g_e1    = sc + OFF_E1;
    float* g_enc   = sc + OFF_ENC;
    float* g_y     = sc + OFF_Y;
    float* g_ha    = sc + OFF_HA;
    float* g_hb    = sc + OFF_HB;
    float* g_preds = sc + OFF_PREDS;
    float* g_d1    = sc + OFF_D1;
    float* g_dec   = sc + OFF_DEC;

    // 1) instance norm stats + normalized transposed input
    stats_xnc_kernel<<<256, 256>>>(x_enc, g_xnc, g_mean, g_std);

    // 2) circulant kernel + matrix
    kker_kernel<<<4, 512>>>(mask_w, g_kker);
    kc_kernel<<<dim3(512, 4), 512>>>(g_kker, g_kc);

    // 3) Fourier filter GEMM with fused permutation into Xi layout
    gemm128<false, true><<<dim3(8192 / 128, 512 / 128, NB), 256>>>(
        g_kc, g_xnc, nullptr, g_xi,
        512, 512, 512, 0,
        512L * 512, 0, 0, 2048L * 2048);

    // 4) encoder MLP
    gemm128<true, false><<<dim3(1024 / 128, 2048 / 128, NB), 256>>>(
        g_xi, enc_w1, enc_b1, g_e1,
        2048, 2048, 2048, 1024,
        2048L * 2048, 1024L * 2048, 1024, 2048L * 1024);
    gemm128<false, false><<<dim3(512 / 128, 2048 / 128, NB), 256>>>(
        g_e1, enc_w2, enc_b2, g_enc,
        1024, 1024, 1024, 512,
        2048L * 1024, 512L * 1024, 512, 2048L * 512);

    // 5) Y = Enc @ Wxh^T
    gemm128<false, false><<<dim3(512 / 128, 2048 / 128, NB), 256>>>(
        g_enc, wxh, nullptr, g_y,
        512, 512, 512, 512,
        2048L * 512, 512L * 512, 0, 2048L * 512);

    // 6) RNN recurrence: h_t = h_{t-1} @ Whh^T + Y_t   (h_0 = Y_0)
    float* hbuf[2] = { g_hb, g_ha };   // t odd -> g_ha
    for (int t = 1; t < 8; t++) {
        const float* Aop = (t == 1) ? g_y : hbuf[(t - 1) & 1];
        int  lda_t = (t == 1) ? 4096 : 512;
        long sA_t  = (t == 1) ? 2048L * 512 : 256L * 512;
        gemm_small<32, 64, 16, 4, 4><<<dim3(512 / 64, 256 / 32, NB), 128>>>(
            Aop, whh, g_y + t * 512, hbuf[t & 1],
            512, lda_t, 512, 512, 4096,
            sA_t, 512L * 512, 2048L * 512, 256L * 512);
    }

    // 7) free-run predictions: preds_s = preds_{s-1} @ Whh^T
    for (int s = 1; s <= 4; s++) {
        const float* Aop = (s == 1) ? g_ha : (g_preds + (s - 2) * 512);
        int  lda_s = (s == 1) ? 512 : 2048;
        long sA_s  = (s == 1) ? 256L * 512 : 256L * 4 * 512;
        gemm_small<32, 64, 16, 4, 4><<<dim3(512 / 64, 256 / 32, NB), 128>>>(
            Aop, whh, nullptr, g_preds + (s - 1) * 512,
            512, lda_s, 512, 2048, 0,
            sA_s, 512L * 512, 0, 256L * 4 * 512);
    }

    // 8) LayerNorm (in place)
    ln_kernel<<<4096, 256>>>(g_preds, ln_g, ln_b);

    // 9) decoder MLP
    gemm128<true, false><<<dim3(1024 / 128, 1024 / 128, NB), 256>>>(
        g_preds, dec_w1, dec_b1, g_d1,
        512, 512, 512, 1024,
        256L * 4 * 512, 1024L * 512, 1024, 1024L * 1024);
    gemm128<false, false><<<dim3(2048 / 128, 1024 / 128, NB), 256>>>(
        g_d1, dec_w2, dec_b2, g_dec,
        1024, 1024, 1024, 2048,
        1024L * 1024, 2048L * 1024, 2048, 1024L * 2048);

    // 10) sum blocks, de-normalize, reshape to [B, 256, 32]
    combine_kernel<<<8192, 256>>>(g_dec, g_std, g_mean, (float*)d_out);
}

// round 8
// speedup vs baseline: 1.1715x; 1.1617x over previous
#include <cuda_runtime.h>
#include <cuda_bf16.h>
#include <math.h>

// ---------------- problem constants ----------------
#define BB   256
#define LL   512
#define CC   32
#define NB   4
#define SEG  64
#define FREQ 8
#define STEP 4
#define DD   512
#define HH   1024
#define FIN  2048   // SEG*CC
#define FF   257    // L/2+1

// ---------------- scratch layout (floats) ----------------
static constexpr long OFF_MEAN  = 0;
static constexpr long OFF_STD   = OFF_MEAN  + 8192;
static constexpr long OFF_XNC   = OFF_STD   + 8192;
static constexpr long OFF_KKER  = OFF_XNC   + 8192L*512;
static constexpr long OFF_KC    = OFF_KKER  + 4L*512;
static constexpr long OFF_D1    = OFF_KC    + 4L*512*512;
static constexpr long OFF_XI    = OFF_D1    + 4L*1024*1024;
static constexpr long OFF_E1    = OFF_XI    + 4L*2048*2048;
static constexpr long OFF_ENC   = OFF_E1    + 4L*2048*1024;
static constexpr long OFF_Y     = OFF_ENC   + 4L*2048*512;
static constexpr long OFF_HA    = OFF_Y     + 4L*2048*512;
static constexpr long OFF_HB    = OFF_HA    + 4L*256*512;
static constexpr long OFF_PREDS = OFF_HB    + 4L*256*512;
static constexpr long OFF_DEC   = OFF_PREDS + 4L*256*4*512;
static constexpr long SCRATCH_TOTAL = OFF_DEC + 4L*1024*2048;

__device__ __align__(16) float g_scratch[SCRATCH_TOTAL];

// ---------------- instance-norm stats + transposed normalized input ----------------
__global__ void stats_xnc_kernel(const float* __restrict__ x, float* __restrict__ xnc,
                                 float* __restrict__ meanO, float* __restrict__ stdO)
{
    int b   = blockIdx.x;
    int tid = threadIdx.x;         // 256
    int c   = tid & 31;
    int ty  = tid >> 5;            // 0..7
    const float* xb = x + (long)b * LL * CC;

    float s = 0.f, s2 = 0.f;
    for (int l = ty; l < LL; l += 8) {
        float v = xb[l * CC + c];
        s += v; s2 += v * v;
    }
    __shared__ float sm[8][32], sm2[8][32];
    sm[ty][c] = s; sm2[ty][c] = s2;
    __syncthreads();
    __shared__ float smean[32], sinv[32];
    if (ty == 0) {
        float S = 0.f, S2 = 0.f;
        #pragma unroll
        for (int i = 0; i < 8; i++) { S += sm[i][c]; S2 += sm2[i][c]; }
        float mu  = S * (1.f / LL);
        float var = S2 * (1.f / LL) - mu * mu;
        float sd  = sqrtf(var + 1e-5f);
        smean[c] = mu; sinv[c] = 1.f / sd;
        meanO[b * 32 + c] = mu;
        stdO [b * 32 + c] = sd;
    }
    __syncthreads();

    __shared__ float tile[32][33];
    for (int l0 = 0; l0 < LL; l0 += 32) {
        #pragma unroll
        for (int i = 0; i < 4; i++) {
            int l = l0 + ty + i * 8;
            tile[ty + i * 8][c] = (xb[l * CC + c] - smean[c]) * sinv[c];
        }
        __syncthreads();
        #pragma unroll
        for (int i = 0; i < 4; i++) {
            int cc = ty + i * 8;
            int ll = c;
            xnc[((long)b * 32 + cc) * LL + l0 + ll] = tile[ll][cc];
        }
        __syncthreads();
    }
}

// ---------------- circular-convolution kernel from mask ----------------
__global__ void kker_kernel(const float* __restrict__ mw, float* __restrict__ kker)
{
    int nb = blockIdx.x;
    int d  = threadIdx.x;          // 512
    __shared__ float m[FF];
    for (int f = threadIdx.x; f < FF; f += 512)
        m[f] = 1.f / (1.f + expf(-mw[nb * FF + f]));
    __syncthreads();
    float acc = m[0] + m[256] * ((d & 1) ? -1.f : 1.f);
    for (int f = 1; f < 256; f++) {
        int k = (f * d) & 511;
        acc += 2.f * m[f] * cospif((float)k * (1.f / 256.f));
    }
    kker[nb * 512 + d] = acc * (1.f / 512.f);
}

// Kc[nb][l][lp] = kker[nb][(l-lp) mod 512]
__global__ void kc_kernel(const float* __restrict__ kker, float* __restrict__ Kc)
{
    int nb = blockIdx.y, l = blockIdx.x;
    __shared__ float kr[512];
    kr[threadIdx.x] = kker[nb * 512 + threadIdx.x];
    __syncthreads();
    int lp = threadIdx.x;
    Kc[((long)nb * 512 + l) * 512 + lp] = kr[(l - lp + 512) & 511];
}

// ---------------- 128x128x8 double-buffered SGEMM (NT), split 4+4 microtile ----------------
// Thread covers rows {bm + ty*4 + i, bm + 64 + ty*4 + i} and cols
// {bn + tx*4 + j, bn + 64 + tx*4 + j} -> fragment LDS at 16B stride = all 32 banks.
// C = A(MxK) @ B(NxK)^T (+bias)(+relu); XIPERM: permuted store into Xi layout
template<bool RELU, bool XIPERM>
__global__ void __launch_bounds__(256)
gemm128(const float* __restrict__ A, const float* __restrict__ Bw,
        const float* __restrict__ bias, float* __restrict__ C,
        int K, int lda, int ldb, int ldc,
        long sA, long sB, long sBias, long sC)
{
    __shared__ __align__(16) float As[2][8][128];
    __shared__ __align__(16) float Bs[2][8][128];

    long z = blockIdx.z;
    A  += z * sA;
    Bw += z * sB;
    C  += z * sC;
    if (bias) bias += z * sBias;

    const int bm = blockIdx.y * 128, bn = blockIdx.x * 128;
    const int tid = threadIdx.x;
    const int tx = tid & 15, ty = tid >> 4;

    // global-load mapping: each thread loads one float4 of A and one of B per k-tile
    const int lrow = tid >> 1;           // 0..127
    const int lk   = (tid & 1) * 4;      // 0 or 4
    const float* Ap = A  + (long)(bm + lrow) * lda + lk;
    const float* Bp = Bw + (long)(bn + lrow) * ldb + lk;

    float acc[8][8];
    #pragma unroll
    for (int i = 0; i < 8; i++)
        #pragma unroll
        for (int j = 0; j < 8; j++) acc[i][j] = 0.f;

    // prologue: load first k-tile
    float4 ra = *(const float4*)Ap;
    float4 rb = *(const float4*)Bp;
    As[0][lk+0][lrow] = ra.x; As[0][lk+1][lrow] = ra.y;
    As[0][lk+2][lrow] = ra.z; As[0][lk+3][lrow] = ra.w;
    Bs[0][lk+0][lrow] = rb.x; Bs[0][lk+1][lrow] = rb.y;
    Bs[0][lk+2][lrow] = rb.z; Bs[0][lk+3][lrow] = rb.w;
    __syncthreads();

    int buf = 0;
    for (int k0 = 8; k0 <= K; k0 += 8) {
        const bool has_next = (k0 < K);
        float4 na, nb4;
        if (has_next) {
            na  = *(const float4*)(Ap + k0);
            nb4 = *(const float4*)(Bp + k0);
        }
        #pragma unroll
        for (int kk = 0; kk < 8; kk++) {
            float a[8], b[8];
            *(float4*)&a[0] = *(const float4*)&As[buf][kk][ty * 4];
            *(float4*)&a[4] = *(const float4*)&As[buf][kk][64 + ty * 4];
            *(float4*)&b[0] = *(const float4*)&Bs[buf][kk][tx * 4];
            *(float4*)&b[4] = *(const float4*)&Bs[buf][kk][64 + tx * 4];
            #pragma unroll
            for (int i = 0; i < 8; i++)
                #pragma unroll
                for (int j = 0; j < 8; j++)
                    acc[i][j] += a[i] * b[j];
        }
        if (has_next) {
            int nbuf = buf ^ 1;
            As[nbuf][lk+0][lrow] = na.x;  As[nbuf][lk+1][lrow] = na.y;
            As[nbuf][lk+2][lrow] = na.z;  As[nbuf][lk+3][lrow] = na.w;
            Bs[nbuf][lk+0][lrow] = nb4.x; Bs[nbuf][lk+1][lrow] = nb4.y;
            Bs[nbuf][lk+2][lrow] = nb4.z; Bs[nbuf][lk+3][lrow] = nb4.w;
            __syncthreads();
            buf = nbuf;
        }
    }

    // epilogue: rows/cols in split 4+4 layout
    #pragma unroll
    for (int ih = 0; ih < 2; ih++) {
        #pragma unroll
        for (int i = 0; i < 4; i++) {
            int m = bm + ih * 64 + ty * 4 + i;
            #pragma unroll
            for (int jh = 0; jh < 2; jh++) {
                int n = bn + jh * 64 + tx * 4;
                float4 o;
                o.x = acc[ih*4+i][jh*4+0]; o.y = acc[ih*4+i][jh*4+1];
                o.z = acc[ih*4+i][jh*4+2]; o.w = acc[ih*4+i][jh*4+3];
                if (bias) {
                    float4 b4 = *(const float4*)&bias[n];
                    o.x += b4.x; o.y += b4.y; o.z += b4.z; o.w += b4.w;
                }
                if (RELU) {
                    o.x = fmaxf(o.x, 0.f); o.y = fmaxf(o.y, 0.f);
                    o.z = fmaxf(o.z, 0.f); o.w = fmaxf(o.w, 0.f);
                }
                if (XIPERM) {
                    long idx = ((long)((n >> 5) * 8 + (m >> 6))) * 2048 + (m & 63) * 32 + (n & 31);
                    *(float4*)&C[idx] = o;
                } else {
                    *(float4*)&C[(long)m * ldc + n] = o;
                }
            }
        }
    }
}

// ---------------- small scalar NT GEMM for RNN steps ----------------
template<int BM, int BN, int BK, int TM, int TN>
__global__ void __launch_bounds__((BM/TM)*(BN/TN))
gemm_small(const float* __restrict__ A, const float* __restrict__ Bw,
           const float* __restrict__ Dadd, float* __restrict__ C,
           int K, int lda, int ldb, int ldc, int ldd,
           long sA, long sB, long sD, long sC)
{
    constexpr int TX = BN / TN, TY = BM / TM, THREADS = TX * TY;
    __shared__ __align__(16) float As[BK][BM + 4];
    __shared__ __align__(16) float Bs[BK][BN + 4];

    long z = blockIdx.z;
    A  += z * sA;
    Bw += z * sB;
    C  += z * sC;
    if (Dadd) Dadd += z * sD;

    const int bm = blockIdx.y * BM, bn = blockIdx.x * BN;
    const int tid = threadIdx.x;
    const int tx = tid % TX, ty = tid / TX;

    float acc[TM][TN];
    #pragma unroll
    for (int i = 0; i < TM; i++)
        #pragma unroll
        for (int j = 0; j < TN; j++) acc[i][j] = 0.f;

    const float* Aptr = A  + (long)bm * lda;
    const float* Bptr = Bw + (long)bn * ldb;

    for (int k0 = 0; k0 < K; k0 += BK) {
        #pragma unroll
        for (int li = tid; li < BM * (BK / 4); li += THREADS) {
            int row = li / (BK / 4), kq = li % (BK / 4);
            float4 v = *(const float4*)(Aptr + (long)row * lda + k0 + kq * 4);
            As[kq*4+0][row] = v.x; As[kq*4+1][row] = v.y;
            As[kq*4+2][row] = v.z; As[kq*4+3][row] = v.w;
        }
        #pragma unroll
        for (int li = tid; li < BN * (BK / 4); li += THREADS) {
            int row = li / (BK / 4), kq = li % (BK / 4);
            float4 v = *(const float4*)(Bptr + (long)row * ldb + k0 + kq * 4);
            Bs[kq*4+0][row] = v.x; Bs[kq*4+1][row] = v.y;
            Bs[kq*4+2][row] = v.z; Bs[kq*4+3][row] = v.w;
        }
        __syncthreads();
        #pragma unroll
        for (int kk = 0; kk < BK; kk++) {
            float a[TM], bv[TN];
            #pragma unroll
            for (int i = 0; i < TM; i += 4) {
                float4 t4 = *(const float4*)&As[kk][ty * TM + i];
                a[i] = t4.x; a[i+1] = t4.y; a[i+2] = t4.z; a[i+3] = t4.w;
            }
            #pragma unroll
            for (int j = 0; j < TN; j += 4) {
                float4 t4 = *(const float4*)&Bs[kk][tx * TN + j];
                bv[j] = t4.x; bv[j+1] = t4.y; bv[j+2] = t4.z; bv[j+3] = t4.w;
            }
            #pragma unroll
            for (int i = 0; i < TM; i++)
                #pragma unroll
                for (int j = 0; j < TN; j++)
                    acc[i][j] += a[i] * bv[j];
        }
        __syncthreads();
    }

    #pragma unroll
    for (int i = 0; i < TM; i++) {
        int m = bm + ty * TM + i;
        #pragma unroll
        for (int j = 0; j < TN; j++) {
            int n = bn + tx * TN + j;
            float v = acc[i][j];
            if (Dadd) v += Dadd[(long)m * ldd + n];
            C[(long)m * ldc + n] = v;
        }
    }
}

// ---------------- LayerNorm over last dim 512 ----------------
__global__ void ln_kernel(float* __restrict__ preds, const float* __restrict__ g,
                          const float* __restrict__ bb)
{
    long row = blockIdx.x;
    int nb = (int)(row >> 10);
    float* p = preds + row * 512;
    int t = threadIdx.x;                    // 256
    float v0 = p[t], v1 = p[t + 256];
    float s = v0 + v1, s2 = v0 * v0 + v1 * v1;
    #pragma unroll
    for (int o = 16; o; o >>= 1) {
        s  += __shfl_xor_sync(0xFFFFFFFFu, s,  o);
        s2 += __shfl_xor_sync(0xFFFFFFFFu, s2, o);
    }
    __shared__ float ws[8], ws2[8];
    if ((t & 31) == 0) { ws[t >> 5] = s; ws2[t >> 5] = s2; }
    __syncthreads();
    float S = 0.f, S2 = 0.f;
    #pragma unroll
    for (int i = 0; i < 8; i++) { S += ws[i]; S2 += ws2[i]; }
    float mu  = S * (1.f / 512.f);
    float inv = rsqrtf(S2 * (1.f / 512.f) - mu * mu + 1e-5f);
    p[t]       = (v0 - mu) * inv * g[nb * 512 + t]       + bb[nb * 512 + t];
    p[t + 256] = (v1 - mu) * inv * g[nb * 512 + t + 256] + bb[nb * 512 + t + 256];
}

// ---------------- sum over blocks + de-normalize ----------------
__global__ void combine_kernel(const float* __restrict__ Dec, const float* __restrict__ stdv,
                               const float* __restrict__ meanv, float* __restrict__ out)
{
    long o = (long)blockIdx.x * 256 + threadIdx.x;
    int b = (int)(o >> 13);
    int r = (int)(o & 8191);
    int t = r >> 5, c = r & 31;
    int s = t >> 6, p = t & 63;
    long idx = ((long)(b * 4 + s)) * 2048 + p * 32 + c;
    const long NBS = 1024L * 2048;
    float acc = Dec[idx] + Dec[idx + NBS] + Dec[idx + 2 * NBS] + Dec[idx + 3 * NBS];
    out[o] = acc * stdv[b * 32 + c] + meanv[b * 32 + c];
}

// ---------------- host orchestration ----------------
extern "C" void kernel_launch(void* const* d_in, const int* in_sizes, int n_in,
                              void* d_out, int out_size)
{
    const float* x_enc  = (const float*)d_in[0];
    const float* mask_w = (const float*)d_in[4];
    const float* enc_w1 = (const float*)d_in[5];
    const float* enc_b1 = (const float*)d_in[6];
    const float* enc_w2 = (const float*)d_in[7];
    const float* enc_b2 = (const float*)d_in[8];
    const float* wxh    = (const float*)d_in[9];
    const float* whh    = (const float*)d_in[10];
    const float* ln_g   = (const float*)d_in[11];
    const float* ln_b   = (const float*)d_in[12];
    const float* dec_w1 = (const float*)d_in[13];
    const float* dec_b1 = (const float*)d_in[14];
    const float* dec_w2 = (const float*)d_in[15];
    const float* dec_b2 = (const float*)d_in[16];

    float* sc = nullptr;
    cudaGetSymbolAddress((void**)&sc, g_scratch);
    float* g_mean  = sc + OFF_MEAN;
    float* g_std   = sc + OFF_STD;
    float* g_xnc   = sc + OFF_XNC;
    float* g_kker  = sc + OFF_KKER;
    float* g_kc    = sc + OFF_KC;
    float* g_xi    = sc + OFF_XI;
    float* g_e1    = sc + OFF_E1;
    float* g_enc   = sc + OFF_ENC;
    float* g_y     = sc + OFF_Y;
    float* g_ha    = sc + OFF_HA;
    float* g_hb    = sc + OFF_HB;
    float* g_preds = sc + OFF_PREDS;
    float* g_d1    = sc + OFF_D1;
    float* g_dec   = sc + OFF_DEC;

    // 1) instance norm stats + normalized transposed input
    stats_xnc_kernel<<<256, 256>>>(x_enc, g_xnc, g_mean, g_std);

    // 2) circulant kernel + matrix
    kker_kernel<<<4, 512>>>(mask_w, g_kker);
    kc_kernel<<<dim3(512, 4), 512>>>(g_kker, g_kc);

    // 3) Fourier filter GEMM with fused permutation into Xi layout
    gemm128<false, true><<<dim3(8192 / 128, 512 / 128, NB), 256>>>(
        g_kc, g_xnc, nullptr, g_xi,
        512, 512, 512, 0,
        512L * 512, 0, 0, 2048L * 2048);

    // 4) encoder MLP
    gemm128<true, false><<<dim3(1024 / 128, 2048 / 128, NB), 256>>>(
        g_xi, enc_w1, enc_b1, g_e1,
        2048, 2048, 2048, 1024,
        2048L * 2048, 1024L * 2048, 1024, 2048L * 1024);
    gemm128<false, false><<<dim3(512 / 128, 2048 / 128, NB), 256>>>(
        g_e1, enc_w2, enc_b2, g_enc,
        1024, 1024, 1024, 512,
        2048L * 1024, 512L * 1024, 512, 2048L * 512);

    // 5) Y = Enc @ Wxh^T
    gemm128<false, false><<<dim3(512 / 128, 2048 / 128, NB), 256>>>(
        g_enc, wxh, nullptr, g_y,
        512, 512, 512, 512,
        2048L * 512, 512L * 512, 0, 2048L * 512);

    // 6) RNN recurrence: h_t = h_{t-1} @ Whh^T + Y_t   (h_0 = Y_0)
    float* hbuf[2] = { g_hb, g_ha };   // t odd -> g_ha
    for (int t = 1; t < 8; t++) {
        const float* Aop = (t == 1) ? g_y : hbuf[(t - 1) & 1];
        int  lda_t = (t == 1) ? 4096 : 512;
        long sA_t  = (t == 1) ? 2048L * 512 : 256L * 512;
        gemm_small<32, 64, 16, 4, 4><<<dim3(512 / 64, 256 / 32, NB), 128>>>(
            Aop, whh, g_y + t * 512, hbuf[t & 1],
            512, lda_t, 512, 512, 4096,
            sA_t, 512L * 512, 2048L * 512, 256L * 512);
    }

    // 7) free-run predictions: preds_s = preds_{s-1} @ Whh^T
    for (int s = 1; s <= 4; s++) {
        const float* Aop = (s == 1) ? g_ha : (g_preds + (s - 2) * 512);
        int  lda_s = (s == 1) ? 512 : 2048;
        long sA_s  = (s == 1) ? 256L * 512 : 256L * 4 * 512;
        gemm_small<32, 64, 16, 4, 4><<<dim3(512 / 64, 256 / 32, NB), 128>>>(
            Aop, whh, nullptr, g_preds + (s - 1) * 512,
            512, lda_s, 512, 2048, 0,
            sA_s, 512L * 512, 0, 256L * 4 * 512);
    }

    // 8) LayerNorm (in place)
    ln_kernel<<<4096, 256>>>(g_preds, ln_g, ln_b);

    // 9) decoder MLP
    gemm128<true, false><<<dim3(1024 / 128, 1024 / 128, NB), 256>>>(
        g_preds, dec_w1, dec_b1, g_d1,
        512, 512, 512, 1024,
        256L * 4 * 512, 1024L * 512, 1024, 1024L * 1024);
    gemm128<false, false><<<dim3(2048 / 128, 1024 / 128, NB), 256>>>(
        g_d1, dec_w2, dec_b2, g_dec,
        1024, 1024, 1024, 2048,
        1024L * 1024, 2048L * 1024, 2048, 1024L * 2048);

    // 10) sum blocks, de-normalize, reshape to [B, 256, 32]
    combine_kernel<<<8192, 256>>>(g_dec, g_std, g_mean, (float*)d_out);
}

// round 10
// speedup vs baseline: 2.0804x; 1.7759x over previous
#include <cuda_runtime.h>
#include <math.h>
#include <stdint.h>

// ---------------- problem constants ----------------
#define BB   256
#define LL   512
#define CC   32
#define NB   4
#define SEG  64
#define FREQ 8
#define STEP 4
#define DD   512
#define HH   1024
#define FIN  2048
#define FF   257

// ---------------- fp32 scratch ----------------
static constexpr long OFF_MEAN  = 0;
static constexpr long OFF_STD   = OFF_MEAN  + 8192;
static constexpr long OFF_KKER  = OFF_STD   + 8192;
static constexpr long OFF_Y     = OFF_KKER  + 4L*512;
static constexpr long OFF_HA    = OFF_Y     + 4L*2048*512;
static constexpr long OFF_HB    = OFF_HA    + 4L*256*512;
static constexpr long OFF_PREDS = OFF_HB    + 4L*256*512;
static constexpr long OFF_DEC   = OFF_PREDS + 4L*1024*512;
static constexpr long F_TOTAL   = OFF_DEC   + 4L*1024*2048;
__device__ __align__(16) float g_scratch[F_TOTAL];

// ---------------- bf16 (hi,lo) scratch, stored as ushort ----------------
static constexpr long BF_XNC_H = 0;
static constexpr long BF_XNC_L = BF_XNC_H + 8192L*512;
static constexpr long BF_KC_H  = BF_XNC_L + 8192L*512;
static constexpr long BF_KC_L  = BF_KC_H  + 4L*512*512;
static constexpr long BF_XI_H  = BF_KC_L  + 4L*512*512;
static constexpr long BF_XI_L  = BF_XI_H  + 4L*2048*2048;
static constexpr long BF_EW1_H = BF_XI_L  + 4L*2048*2048;
static constexpr long BF_EW1_L = BF_EW1_H + 4L*1024*2048;
static constexpr long BF_E1_H  = BF_EW1_L + 4L*1024*2048;
static constexpr long BF_E1_L  = BF_E1_H  + 4L*2048*1024;
static constexpr long BF_EW2_H = BF_E1_L  + 4L*2048*1024;
static constexpr long BF_EW2_L = BF_EW2_H + 4L*512*1024;
static constexpr long BF_ENC_H = BF_EW2_L + 4L*512*1024;
static constexpr long BF_ENC_L = BF_ENC_H + 4L*2048*512;
static constexpr long BF_WXH_H = BF_ENC_L + 4L*2048*512;
static constexpr long BF_WXH_L = BF_WXH_H + 4L*512*512;
static constexpr long BF_PRE_H = BF_WXH_L + 4L*512*512;
static constexpr long BF_PRE_L = BF_PRE_H + 4L*1024*512;
static constexpr long BF_DW1_H = BF_PRE_L + 4L*1024*512;
static constexpr long BF_DW1_L = BF_DW1_H + 4L*1024*512;
static constexpr long BF_D1_H  = BF_DW1_L + 4L*1024*512;
static constexpr long BF_D1_L  = BF_D1_H  + 4L*1024*1024;
static constexpr long BF_DW2_H = BF_D1_L  + 4L*1024*1024;
static constexpr long BF_DW2_L = BF_DW2_H + 4L*2048*1024;
static constexpr long BF_TOTAL = BF_DW2_L + 4L*2048*1024;
__device__ __align__(16) unsigned short g_bf[BF_TOTAL];

// ---------------- bf16 split helpers (no cuda_bf16 API) ----------------
__device__ __forceinline__ uint32_t bfbits(float x) {       // RN-even bf16 bits
    uint32_t b = __float_as_uint(x);
    return (b + 0x7FFFu + ((b >> 16) & 1u)) >> 16;
}
__device__ __forceinline__ float bffloat(uint32_t h) { return __uint_as_float(h << 16); }

// ---------------- mma / ldmatrix ----------------
__device__ __forceinline__ void ldsm4(uint32_t* r, uint32_t a) {
    asm volatile("ldmatrix.sync.aligned.m8n8.x4.shared.b16 {%0,%1,%2,%3}, [%4];"
        : "=r"(r[0]), "=r"(r[1]), "=r"(r[2]), "=r"(r[3]) : "r"(a));
}
__device__ __forceinline__ void mma_bf(float* c, const uint32_t* a, uint32_t b0, uint32_t b1) {
    asm volatile("mma.sync.aligned.m16n8k16.row.col.f32.bf16.bf16.f32 "
        "{%0,%1,%2,%3},{%4,%5,%6,%7},{%8,%9},{%0,%1,%2,%3};"
        : "+f"(c[0]), "+f"(c[1]), "+f"(c[2]), "+f"(c[3])
        : "r"(a[0]), "r"(a[1]), "r"(a[2]), "r"(a[3]), "r"(b0), "r"(b1));
}
__device__ __forceinline__ uint32_t smem_u32(const void* p) {
    uint32_t a;
    asm("{ .reg .u64 t; cvta.to.shared.u64 t, %1; cvt.u32.u64 %0, t; }" : "=r"(a) : "l"(p));
    return a;
}

// ============ bf16 3-term tensor-core NT GEMM ============
// C = A(MxK) @ B(NxK)^T (+bias)(+relu). A,B given as (hi,lo) bf16 arrays.
// OUTB: write (hi,lo) bf16 outputs; else fp32. XIPERM: permuted Xi-layout store.
static constexpr int HG_SMEM = 8 * 10240;   // 2 buf x 4 tiles x 128 rows x 80B
template<bool RELU, bool XIPERM, bool OUTB>
__global__ void __launch_bounds__(256, 1)
hgemm(const unsigned short* __restrict__ Ah, const unsigned short* __restrict__ Al,
      const unsigned short* __restrict__ Bh, const unsigned short* __restrict__ Bl,
      const float* __restrict__ bias,
      float* __restrict__ Cf, unsigned short* __restrict__ Ch, unsigned short* __restrict__ Cl,
      int K, int lda, int ldb, int ldc,
      long sA, long sB, long sBias, long sC)
{
    extern __shared__ __align__(16) char sm_[];
    const int tid = threadIdx.x, wid = tid >> 5, lane = tid & 31;
    long z = blockIdx.z;
    Ah += z * sA; Al += z * sA; Bh += z * sB; Bl += z * sB;
    if (bias) bias += z * sBias;
    if (OUTB) { Ch += z * sC; Cl += z * sC; } else { Cf += z * sC; }
    const int bm = blockIdx.y * 128, bn = blockIdx.x * 128;

    const int mw = wid >> 2, nw = wid & 3;       // warp tile: rows mw*64, cols nw*32
    const int sub = lane >> 3, l7 = lane & 7;
    const uint32_t sbase = smem_u32(sm_);
    const uint32_t aoff = (uint32_t)((mw * 64 + l7 + (sub & 1) * 8) * 80 + (sub >> 1) * 16);
    const uint32_t boff = (uint32_t)((nw * 32 + l7 + (sub >> 1) * 8) * 80 + (sub & 1) * 16);

    float acc[4][4][4];
    #pragma unroll
    for (int f = 0; f < 4; f++)
        #pragma unroll
        for (int g = 0; g < 4; g++)
            #pragma unroll
            for (int r = 0; r < 4; r++) acc[f][g][r] = 0.f;

    const unsigned short* srcs[4] = { Ah, Al, Bh, Bl };
    const int nC = K >> 5;

    // prologue: chunk 0 -> buf 0
    #pragma unroll
    for (int t = 0; t < 4; t++) {
        const unsigned short* src = srcs[t];
        int base = (t < 2) ? bm : bn, ld = (t < 2) ? lda : ldb;
        #pragma unroll
        for (int u = 0; u < 2; u++) {
            int unit = tid + u * 256, row = unit >> 2, q = unit & 3;
            uint4 v = *(const uint4*)(src + (long)(base + row) * ld + q * 8);
            *(uint4*)(sm_ + t * 10240 + row * 80 + q * 16) = v;
        }
    }
    __syncthreads();

    int buf = 0;
    for (int i = 0; i < nC; i++) {
        const bool hn = (i + 1 < nC);
        uint4 st[8];
        if (hn) {
            int k0 = (i + 1) << 5;
            #pragma unroll
            for (int t = 0; t < 4; t++) {
                const unsigned short* src = srcs[t];
                int base = (t < 2) ? bm : bn, ld = (t < 2) ? lda : ldb;
                #pragma unroll
                for (int u = 0; u < 2; u++) {
                    int unit = tid + u * 256, row = unit >> 2, q = unit & 3;
                    st[t * 2 + u] = *(const uint4*)(src + (long)(base + row) * ld + k0 + q * 8);
                }
            }
        }
        uint32_t tb = (uint32_t)(buf * 40960);
        #pragma unroll
        for (int kh = 0; kh < 2; kh++) {
            uint32_t kb = (uint32_t)(kh * 32);
            uint32_t ah[4][4], al4[4][4], bh2[2][4], bl2[2][4];
            #pragma unroll
            for (int f = 0; f < 4; f++) {
                ldsm4(ah[f],  sbase + tb +     0 + aoff + f * 1280 + kb);
                ldsm4(al4[f], sbase + tb + 10240 + aoff + f * 1280 + kb);
            }
            #pragma unroll
            for (int g = 0; g < 2; g++) {
                ldsm4(bh2[g], sbase + tb + 20480 + boff + g * 1280 + kb);
                ldsm4(bl2[g], sbase + tb + 30720 + boff + g * 1280 + kb);
            }
            #pragma unroll
            for (int f = 0; f < 4; f++)
                #pragma unroll
                for (int g = 0; g < 2; g++) {
                    mma_bf(acc[f][2*g],   ah[f],  bh2[g][0], bh2[g][1]);
                    mma_bf(acc[f][2*g],   ah[f],  bl2[g][0], bl2[g][1]);
                    mma_bf(acc[f][2*g],   al4[f], bh2[g][0], bh2[g][1]);
                    mma_bf(acc[f][2*g+1], ah[f],  bh2[g][2], bh2[g][3]);
                    mma_bf(acc[f][2*g+1], ah[f],  bl2[g][2], bl2[g][3]);
                    mma_bf(acc[f][2*g+1], al4[f], bh2[g][2], bh2[g][3]);
                }
        }
        if (hn) {
            int nb2 = buf ^ 1;
            #pragma unroll
            for (int t = 0; t < 4; t++)
                #pragma unroll
                for (int u = 0; u < 2; u++) {
                    int unit = tid + u * 256, row = unit >> 2, q = unit & 3;
                    *(uint4*)(sm_ + nb2 * 40960 + t * 10240 + row * 80 + q * 16) = st[t * 2 + u];
                }
            __syncthreads();
            buf = nb2;
        }
    }

    // epilogue: frag (f,g2): rows bm+mw*64+f*16+gid(+8), cols bn+nw*32+g2*8+tig*2
    const int gid = lane >> 2, tig = lane & 3;
    #pragma unroll
    for (int f = 0; f < 4; f++) {
        #pragma unroll
        for (int g2 = 0; g2 < 4; g2++) {
            int n0 = bn + nw * 32 + g2 * 8 + tig * 2;
            float bx = 0.f, by = 0.f;
            if (bias) { float2 b2 = *(const float2*)&bias[n0]; bx = b2.x; by = b2.y; }
            #pragma unroll
            for (int h = 0; h < 2; h++) {
                int m = bm + mw * 64 + f * 16 + gid + h * 8;
                float v0 = acc[f][g2][h * 2 + 0] + bx;
                float v1 = acc[f][g2][h * 2 + 1] + by;
                if (RELU) { v0 = fmaxf(v0, 0.f); v1 = fmaxf(v1, 0.f); }
                long idx;
                if (XIPERM) idx = ((long)((n0 >> 5) * 8 + (m >> 6))) * 2048 + (m & 63) * 32 + (n0 & 31);
                else        idx = (long)m * ldc + n0;
                if (OUTB) {
                    uint32_t h0 = bfbits(v0), h1 = bfbits(v1);
                    uint32_t l0 = bfbits(v0 - bffloat(h0)), l1 = bfbits(v1 - bffloat(h1));
                    *(uint32_t*)(Ch + idx) = (h1 << 16) | h0;
                    *(uint32_t*)(Cl + idx) = (l1 << 16) | l0;
                } else {
                    *(float2*)(Cf + idx) = make_float2(v0, v1);
                }
            }
        }
    }
}

// ---------------- fp32 -> (hi,lo) bf16 conversion ----------------
__global__ void conv_bf16(const float* __restrict__ x, unsigned short* __restrict__ h,
                          unsigned short* __restrict__ l, long n4)
{
    long i = (long)blockIdx.x * 256 + threadIdx.x;
    if (i >= n4) return;
    float4 v = *(const float4*)(x + i * 4);
    uint32_t h0 = bfbits(v.x), h1 = bfbits(v.y), h2 = bfbits(v.z), h3 = bfbits(v.w);
    uint2 hp; hp.x = (h1 << 16) | h0; hp.y = (h3 << 16) | h2;
    uint32_t l0 = bfbits(v.x - bffloat(h0)), l1 = bfbits(v.y - bffloat(h1));
    uint32_t l2 = bfbits(v.z - bffloat(h2)), l3 = bfbits(v.w - bffloat(h3));
    uint2 lp; lp.x = (l1 << 16) | l0; lp.y = (l3 << 16) | l2;
    *(uint2*)(h + i * 4) = hp;
    *(uint2*)(l + i * 4) = lp;
}

// ---------------- instance-norm stats + transposed normalized input (bf16 out) ----------------
__global__ void stats_xnc_kernel(const float* __restrict__ x,
                                 unsigned short* __restrict__ xh, unsigned short* __restrict__ xl,
                                 float* __restrict__ meanO, float* __restrict__ stdO)
{
    int b = blockIdx.x;
    int tid = threadIdx.x;
    int c = tid & 31, ty = tid >> 5;
    const float* xb = x + (long)b * LL * CC;

    float s = 0.f, s2 = 0.f;
    for (int l = ty; l < LL; l += 8) {
        float v = xb[l * CC + c];
        s += v; s2 += v * v;
    }
    __shared__ float sm[8][32], sm2[8][32];
    sm[ty][c] = s; sm2[ty][c] = s2;
    __syncthreads();
    __shared__ float smean[32], sinv[32];
    if (ty == 0) {
        float S = 0.f, S2 = 0.f;
        #pragma unroll
        for (int i = 0; i < 8; i++) { S += sm[i][c]; S2 += sm2[i][c]; }
        float mu = S * (1.f / LL);
        float var = S2 * (1.f / LL) - mu * mu;
        float sd = sqrtf(var + 1e-5f);
        smean[c] = mu; sinv[c] = 1.f / sd;
        meanO[b * 32 + c] = mu;
        stdO [b * 32 + c] = sd;
    }
    __syncthreads();

    __shared__ float tile[32][33];
    for (int l0 = 0; l0 < LL; l0 += 32) {
        #pragma unroll
        for (int i = 0; i < 4; i++) {
            int l = l0 + ty + i * 8;
            tile[ty + i * 8][c] = (xb[l * CC + c] - smean[c]) * sinv[c];
        }
        __syncthreads();
        #pragma unroll
        for (int i = 0; i < 4; i++) {
            int cc = ty + i * 8;
            int ll = c;
            float v = tile[ll][cc];
            long idx = ((long)b * 32 + cc) * LL + l0 + ll;
            uint32_t hb = bfbits(v);
            xh[idx] = (unsigned short)hb;
            xl[idx] = (unsigned short)bfbits(v - bffloat(hb));
        }
        __syncthreads();
    }
}

// ---------------- circular-convolution kernel from mask ----------------
__global__ void kker_kernel(const float* __restrict__ mw, float* __restrict__ kker)
{
    int nb = blockIdx.x;
    int d = threadIdx.x;
    __shared__ float m[FF];
    for (int f = threadIdx.x; f < FF; f += 512)
        m[f] = 1.f / (1.f + expf(-mw[nb * FF + f]));
    __syncthreads();
    float acc = m[0] + m[256] * ((d & 1) ? -1.f : 1.f);
    for (int f = 1; f < 256; f++) {
        int k = (f * d) & 511;
        acc += 2.f * m[f] * cospif((float)k * (1.f / 256.f));
    }
    kker[nb * 512 + d] = acc * (1.f / 512.f);
}

// Kc[nb][l][lp] = kker[nb][(l-lp) mod 512] -> bf16 hi/lo
__global__ void kc_kernel(const float* __restrict__ kker,
                          unsigned short* __restrict__ kh, unsigned short* __restrict__ kl)
{
    int nb = blockIdx.y, l = blockIdx.x;
    __shared__ float kr[512];
    kr[threadIdx.x] = kker[nb * 512 + threadIdx.x];
    __syncthreads();
    int lp = threadIdx.x;
    float v = kr[(l - lp + 512) & 511];
    long idx = ((long)nb * 512 + l) * 512 + lp;
    uint32_t hb = bfbits(v);
    kh[idx] = (unsigned short)hb;
    kl[idx] = (unsigned short)bfbits(v - bffloat(hb));
}

// ---------------- small fp32 NT GEMM for RNN steps ----------------
template<int BM, int BN, int BK, int TM, int TN>
__global__ void __launch_bounds__((BM/TM)*(BN/TN))
gemm_small(const float* __restrict__ A, const float* __restrict__ Bw,
           const float* __restrict__ Dadd, float* __restrict__ C,
           int K, int lda, int ldb, int ldc, int ldd,
           long sA, long sB, long sD, long sC)
{
    constexpr int TX = BN / TN, TY = BM / TM, THREADS = TX * TY;
    __shared__ __align__(16) float As[BK][BM + 4];
    __shared__ __align__(16) float Bs[BK][BN + 4];

    long z = blockIdx.z;
    A += z * sA; Bw += z * sB; C += z * sC;
    if (Dadd) Dadd += z * sD;

    const int bm = blockIdx.y * BM, bn = blockIdx.x * BN;
    const int tid = threadIdx.x;
    const int tx = tid % TX, ty = tid / TX;

    float acc[TM][TN];
    #pragma unroll
    for (int i = 0; i < TM; i++)
        #pragma unroll
        for (int j = 0; j < TN; j++) acc[i][j] = 0.f;

    const float* Aptr = A + (long)bm * lda;
    const float* Bptr = Bw + (long)bn * ldb;

    for (int k0 = 0; k0 < K; k0 += BK) {
        #pragma unroll
        for (int li = tid; li < BM * (BK / 4); li += THREADS) {
            int row = li / (BK / 4), kq = li % (BK / 4);
            float4 v = *(const float4*)(Aptr + (long)row * lda + k0 + kq * 4);
            As[kq*4+0][row] = v.x; As[kq*4+1][row] = v.y;
            As[kq*4+2][row] = v.z; As[kq*4+3][row] = v.w;
        }
        #pragma unroll
        for (int li = tid; li < BN * (BK / 4); li += THREADS) {
            int row = li / (BK / 4), kq = li % (BK / 4);
            float4 v = *(const float4*)(Bptr + (long)row * ldb + k0 + kq * 4);
            Bs[kq*4+0][row] = v.x; Bs[kq*4+1][row] = v.y;
            Bs[kq*4+2][row] = v.z; Bs[kq*4+3][row] = v.w;
        }
        __syncthreads();
        #pragma unroll
        for (int kk = 0; kk < BK; kk++) {
            float a[TM], bv[TN];
            #pragma unroll
            for (int i = 0; i < TM; i += 4) {
                float4 t4 = *(const float4*)&As[kk][ty * TM + i];
                a[i] = t4.x; a[i+1] = t4.y; a[i+2] = t4.z; a[i+3] = t4.w;
            }
            #pragma unroll
            for (int j = 0; j < TN; j += 4) {
                float4 t4 = *(const float4*)&Bs[kk][tx * TN + j];
                bv[j] = t4.x; bv[j+1] = t4.y; bv[j+2] = t4.z; bv[j+3] = t4.w;
            }
            #pragma unroll
            for (int i = 0; i < TM; i++)
                #pragma unroll
                for (int j = 0; j < TN; j++)
                    acc[i][j] += a[i] * bv[j];
        }
        __syncthreads();
    }

    #pragma unroll
    for (int i = 0; i < TM; i++) {
        int m = bm + ty * TM + i;
        #pragma unroll
        for (int j = 0; j < TN; j++) {
            int n = bn + tx * TN + j;
            float v = acc[i][j];
            if (Dadd) v += Dadd[(long)m * ldd + n];
            C[(long)m * ldc + n] = v;
        }
    }
}

// ---------------- LayerNorm (fp32 in, bf16 hi/lo out) ----------------
__global__ void ln_kernel(const float* __restrict__ preds,
                          unsigned short* __restrict__ ph, unsigned short* __restrict__ pl,
                          const float* __restrict__ g, const float* __restrict__ bb)
{
    long row = blockIdx.x;                  // nb*1024 + b*4 + s
    int nb = (int)(row >> 10);
    const float* p = preds + row * 512;
    int t = threadIdx.x;                    // 256
    float v0 = p[t], v1 = p[t + 256];
    float s = v0 + v1, s2 = v0 * v0 + v1 * v1;
    #pragma unroll
    for (int o = 16; o; o >>= 1) {
        s  += __shfl_xor_sync(0xFFFFFFFFu, s,  o);
        s2 += __shfl_xor_sync(0xFFFFFFFFu, s2, o);
    }
    __shared__ float ws[8], ws2[8];
    if ((t & 31) == 0) { ws[t >> 5] = s; ws2[t >> 5] = s2; }
    __syncthreads();
    float S = 0.f, S2 = 0.f;
    #pragma unroll
    for (int i = 0; i < 8; i++) { S += ws[i]; S2 += ws2[i]; }
    float mu = S * (1.f / 512.f);
    float inv = rsqrtf(S2 * (1.f / 512.f) - mu * mu + 1e-5f);
    float o0 = (v0 - mu) * inv * g[nb * 512 + t]       + bb[nb * 512 + t];
    float o1 = (v1 - mu) * inv * g[nb * 512 + t + 256] + bb[nb * 512 + t + 256];
    long i0 = row * 512 + t, i1 = i0 + 256;
    uint32_t h0 = bfbits(o0), h1 = bfbits(o1);
    ph[i0] = (unsigned short)h0; pl[i0] = (unsigned short)bfbits(o0 - bffloat(h0));
    ph[i1] = (unsigned short)h1; pl[i1] = (unsigned short)bfbits(o1 - bffloat(h1));
}

// ---------------- sum over blocks + de-normalize ----------------
__global__ void combine_kernel(const float* __restrict__ Dec, const float* __restrict__ stdv,
                               const float* __restrict__ meanv, float* __restrict__ out)
{
    long o = (long)blockIdx.x * 256 + threadIdx.x;
    int b = (int)(o >> 13);
    int r = (int)(o & 8191);
    int t = r >> 5, c = r & 31;
    int s = t >> 6, p = t & 63;
    long idx = ((long)(b * 4 + s)) * 2048 + p * 32 + c;
    const long NBS = 1024L * 2048;
    float acc = Dec[idx] + Dec[idx + NBS] + Dec[idx + 2 * NBS] + Dec[idx + 3 * NBS];
    out[o] = acc * stdv[b * 32 + c] + meanv[b * 32 + c];
}

// ---------------- host orchestration ----------------
extern "C" void kernel_launch(void* const* d_in, const int* in_sizes, int n_in,
                              void* d_out, int out_size)
{
    const float* x_enc  = (const float*)d_in[0];
    const float* mask_w = (const float*)d_in[4];
    const float* enc_w1 = (const float*)d_in[5];
    const float* enc_b1 = (const float*)d_in[6];
    const float* enc_w2 = (const float*)d_in[7];
    const float* enc_b2 = (const float*)d_in[8];
    const float* wxh    = (const float*)d_in[9];
    const float* whh    = (const float*)d_in[10];
    const float* ln_g   = (const float*)d_in[11];
    const float* ln_b   = (const float*)d_in[12];
    const float* dec_w1 = (const float*)d_in[13];
    const float* dec_b1 = (const float*)d_in[14];
    const float* dec_w2 = (const float*)d_in[15];
    const float* dec_b2 = (const float*)d_in[16];

    float* sc = nullptr;
    cudaGetSymbolAddress((void**)&sc, g_scratch);
    unsigned short* bf = nullptr;
    cudaGetSymbolAddress((void**)&bf, g_bf);

    float* g_mean  = sc + OFF_MEAN;
    float* g_std   = sc + OFF_STD;
    float* g_kker  = sc + OFF_KKER;
    float* g_y     = sc + OFF_Y;
    float* g_ha    = sc + OFF_HA;
    float* g_hb    = sc + OFF_HB;
    float* g_preds = sc + OFF_PREDS;
    float* g_dec   = sc + OFF_DEC;

    cudaFuncSetAttribute(hgemm<false, true,  true >, cudaFuncAttributeMaxDynamicSharedMemorySize, HG_SMEM);
    cudaFuncSetAttribute(hgemm<true,  false, true >, cudaFuncAttributeMaxDynamicSharedMemorySize, HG_SMEM);
    cudaFuncSetAttribute(hgemm<false, false, true >, cudaFuncAttributeMaxDynamicSharedMemorySize, HG_SMEM);
    cudaFuncSetAttribute(hgemm<false, false, false>, cudaFuncAttributeMaxDynamicSharedMemorySize, HG_SMEM);

    // 0) weight conversions
    conv_bf16<<<(int)(4L*1024*2048/4/256), 256>>>(enc_w1, bf + BF_EW1_H, bf + BF_EW1_L, 4L*1024*2048/4);
    conv_bf16<<<(int)(4L*512*1024 /4/256), 256>>>(enc_w2, bf + BF_EW2_H, bf + BF_EW2_L, 4L*512*1024/4);
    conv_bf16<<<(int)(4L*512*512  /4/256), 256>>>(wxh,    bf + BF_WXH_H, bf + BF_WXH_L, 4L*512*512/4);
    conv_bf16<<<(int)(4L*1024*512 /4/256), 256>>>(dec_w1, bf + BF_DW1_H, bf + BF_DW1_L, 4L*1024*512/4);
    conv_bf16<<<(int)(4L*2048*1024/4/256), 256>>>(dec_w2, bf + BF_DW2_H, bf + BF_DW2_L, 4L*2048*1024/4);

    // 1) instance norm stats + normalized transposed input (bf16)
    stats_xnc_kernel<<<256, 256>>>(x_enc, bf + BF_XNC_H, bf + BF_XNC_L, g_mean, g_std);

    // 2) circulant kernel + matrix (bf16)
    kker_kernel<<<4, 512>>>(mask_w, g_kker);
    kc_kernel<<<dim3(512, 4), 512>>>(g_kker, bf + BF_KC_H, bf + BF_KC_L);

    // 3) Fourier filter GEMM -> Xi (bf16, permuted layout)
    hgemm<false, true, true><<<dim3(64, 4, NB), 256, HG_SMEM>>>(
        bf + BF_KC_H, bf + BF_KC_L, bf + BF_XNC_H, bf + BF_XNC_L,
        nullptr, nullptr, bf + BF_XI_H, bf + BF_XI_L,
        512, 512, 512, 0,
        512L * 512, 0, 0, 2048L * 2048);

    // 4) encoder MLP
    hgemm<true, false, true><<<dim3(8, 16, NB), 256, HG_SMEM>>>(
        bf + BF_XI_H, bf + BF_XI_L, bf + BF_EW1_H, bf + BF_EW1_L,
        enc_b1, nullptr, bf + BF_E1_H, bf + BF_E1_L,
        2048, 2048, 2048, 1024,
        2048L * 2048, 1024L * 2048, 1024, 2048L * 1024);
    hgemm<false, false, true><<<dim3(4, 16, NB), 256, HG_SMEM>>>(
        bf + BF_E1_H, bf + BF_E1_L, bf + BF_EW2_H, bf + BF_EW2_L,
        enc_b2, nullptr, bf + BF_ENC_H, bf + BF_ENC_L,
        1024, 1024, 1024, 512,
        2048L * 1024, 512L * 1024, 512, 2048L * 512);

    // 5) Y = Enc @ Wxh^T (fp32 out)
    hgemm<false, false, false><<<dim3(4, 16, NB), 256, HG_SMEM>>>(
        bf + BF_ENC_H, bf + BF_ENC_L, bf + BF_WXH_H, bf + BF_WXH_L,
        nullptr, g_y, nullptr, nullptr,
        512, 512, 512, 512,
        2048L * 512, 512L * 512, 0, 2048L * 512);

    // 6) RNN recurrence (fp32): h_t = h_{t-1} @ Whh^T + Y_t  (h_0 = Y_0)
    float* hbuf[2] = { g_hb, g_ha };
    for (int t = 1; t < 8; t++) {
        const float* Aop = (t == 1) ? g_y : hbuf[(t - 1) & 1];
        int  lda_t = (t == 1) ? 4096 : 512;
        long sA_t  = (t == 1) ? 2048L * 512 : 256L * 512;
        gemm_small<32, 64, 16, 4, 4><<<dim3(8, 8, NB), 128>>>(
            Aop, whh, g_y + t * 512, hbuf[t & 1],
            512, lda_t, 512, 512, 4096,
            sA_t, 512L * 512, 2048L * 512, 256L * 512);
    }

    // 7) free-run predictions (fp32)
    for (int s = 1; s <= 4; s++) {
        const float* Aop = (s == 1) ? g_ha : (g_preds + (s - 2) * 512);
        int  lda_s = (s == 1) ? 512 : 2048;
        long sA_s  = (s == 1) ? 256L * 512 : 256L * 4 * 512;
        gemm_small<32, 64, 16, 4, 4><<<dim3(8, 8, NB), 128>>>(
            Aop, whh, nullptr, g_preds + (s - 1) * 512,
            512, lda_s, 512, 2048, 0,
            sA_s, 512L * 512, 0, 256L * 4 * 512);
    }

    // 8) LayerNorm -> bf16 preds
    ln_kernel<<<4096, 256>>>(g_preds, bf + BF_PRE_H, bf + BF_PRE_L, ln_g, ln_b);

    // 9) decoder MLP
    hgemm<true, false, true><<<dim3(8, 8, NB), 256, HG_SMEM>>>(
        bf + BF_PRE_H, bf + BF_PRE_L, bf + BF_DW1_H, bf + BF_DW1_L,
        dec_b1, nullptr, bf + BF_D1_H, bf + BF_D1_L,
        512, 512, 512, 1024,
        1024L * 512, 1024L * 512, 1024, 1024L * 1024);
    hgemm<false, false, false><<<dim3(16, 8, NB), 256, HG_SMEM>>>(
        bf + BF_D1_H, bf + BF_D1_L, bf + BF_DW2_H, bf + BF_DW2_L,
        dec_b2, g_dec, nullptr, nullptr,
        1024, 1024, 1024, 2048,
        1024L * 1024, 2048L * 1024, 2048, 1024L * 2048);

    // 10) sum blocks, de-normalize, reshape to [B, 256, 32]
    combine_kernel<<<8192, 256>>>(g_dec, g_std, g_mean, (float*)d_out);
}